// round 5
// baseline (speedup 1.0000x reference)
#include <cuda_runtime.h>
#include <cstdint>

// ---------------------------------------------------------------------------
// C[8192,4096] = A[8192,4096] * W[4096,4096]^T  (fp32 in/out)
// R5: hybrid pipe use. Per CTA (384 thr):
//   warps 0-7 : tf32 mma.sync GEMM, tile 128x128, N region [0,3584)
//   warps 8-11: fp32 FFMA SIMT GEMM, tile 64x64,  N region [3584,4096)
// Disjoint smem, per-role named barriers, per-thread cp.async FIFOs.
// ---------------------------------------------------------------------------

#define MTOT 8192
#define KDIM 4096
#define NDIM 4096
#define NT   3584          // tensor N region; SIMT covers [NT, 4096)

#define BM 128
#define BN 128
#define BK 32
#define KITERS (KDIM / BK)         // 128
#define TSTAGES 3

#define LDSS 36                     // tensor padded row stride (words)
#define TSTAGE_WORDS ((BM + BN) * LDSS)        // 9216
#define TENSOR_WORDS (TSTAGES * TSTAGE_WORDS)  // 27648

// SIMT: tile 64x64, k-major smem [32k x 64+pad]
#define SP 68                       // simt padded k-row stride (words)
#define SSTAGE_WORDS (2 * BK * SP)  // A(32x68)+B(32x68) = 4352
#define SSTAGES 2
#define SIMT_WORDS (SSTAGES * SSTAGE_WORDS)    // 8704

#define SMEM_TOTAL ((TENSOR_WORDS + SIMT_WORDS) * 4)   // 145408 B

#define SIMT_MT (MTOT / 64)         // 128 m-tiles
#define SIMT_NT ((NDIM - NT) / 64)  // 8 n-tiles
#define SIMT_TILES (SIMT_MT * SIMT_NT)  // 1024

// tf32-rounded scratch (device globals: allowed)
__device__ float g_A[(size_t)MTOT * KDIM];
__device__ float g_W[(size_t)NDIM * KDIM];

// ------------------------------- helpers -----------------------------------

__device__ __forceinline__ uint32_t smem_u32(const void* p) {
    uint32_t a;
    asm("{ .reg .u64 t; cvta.to.shared.u64 t, %1; cvt.u32.u64 %0, t; }"
        : "=r"(a) : "l"(p));
    return a;
}
__device__ __forceinline__ float tf32_round(float x) {
    uint32_t u;
    asm("cvt.rna.tf32.f32 %0, %1;" : "=r"(u) : "f"(x));
    return __uint_as_float(u);
}
__device__ __forceinline__ void cp_async16(uint32_t dst, const void* src) {
    asm volatile("cp.async.cg.shared.global [%0], [%1], 16;\n"
                 :: "r"(dst), "l"(src) : "memory");
}
__device__ __forceinline__ void cp_async4(uint32_t dst, const void* src) {
    asm volatile("cp.async.ca.shared.global [%0], [%1], 4;\n"
                 :: "r"(dst), "l"(src) : "memory");
}
__device__ __forceinline__ void cp_commit() {
    asm volatile("cp.async.commit_group;\n" ::: "memory");
}
__device__ __forceinline__ void cp_wait1() {
    asm volatile("cp.async.wait_group 1;\n" ::: "memory");
}
__device__ __forceinline__ void bar_sync(int id, int cnt) {
    asm volatile("bar.sync %0, %1;" :: "r"(id), "r"(cnt) : "memory");
}
__device__ __forceinline__ void mma_m16n8k8(float* c, const uint32_t* a,
                                            const uint32_t* b) {
    asm volatile(
        "mma.sync.aligned.m16n8k8.row.col.f32.tf32.tf32.f32 "
        "{%0,%1,%2,%3}, {%4,%5,%6,%7}, {%8,%9}, {%0,%1,%2,%3};"
        : "+f"(c[0]), "+f"(c[1]), "+f"(c[2]), "+f"(c[3])
        : "r"(a[0]), "r"(a[1]), "r"(a[2]), "r"(a[3]),
          "r"(b[0]), "r"(b[1]));
}

// ------------------------------- prepass ------------------------------------

__global__ void __launch_bounds__(256) prepass_kernel(const float* __restrict__ A,
                                                      const float* __restrict__ W) {
    const long long nA = (long long)MTOT * KDIM / 4;
    const long long nW = (long long)NDIM * KDIM / 4;
    const long long stride = (long long)gridDim.x * blockDim.x;
    for (long long i = (long long)blockIdx.x * blockDim.x + threadIdx.x;
         i < nA + nW; i += stride) {
        const float4* src;
        float4* dst;
        long long j;
        if (i < nA) { src = (const float4*)A; dst = (float4*)g_A; j = i; }
        else        { src = (const float4*)W; dst = (float4*)g_W; j = i - nA; }
        float4 v = src[j];
        v.x = tf32_round(v.x);
        v.y = tf32_round(v.y);
        v.z = tf32_round(v.z);
        v.w = tf32_round(v.w);
        dst[j] = v;
    }
}

// ------------------------------- GEMM ---------------------------------------

__global__ void __launch_bounds__(384, 1) gemm_kernel(float* __restrict__ out,
                                                      const float* __restrict__ Aorig,
                                                      const float* __restrict__ Worig) {
    extern __shared__ float smem[];
    const int tid = threadIdx.x;

    if (tid < 256) {
        // ================= TENSOR ROLE: 8 warps, 128x128 tile =================
        const int lane = tid & 31;
        const int wid = tid >> 5;         // 0..7
        const int warp_m = wid & 1;       // 0..1 -> 64-row strip
        const int warp_n = wid >> 1;      // 0..3 -> 32-col strip
        const int grp = lane >> 2;
        const int tig = lane & 3;

        const int m_base = blockIdx.y * BM;
        const int n_base = blockIdx.x * BN;       // < 3584

        const float* Abase = g_A + (size_t)m_base * KDIM;
        const float* Bbase = g_W + (size_t)n_base * KDIM;

        const int prow = tid >> 3;        // 0..31
        const int pcc = tid & 7;

        float acc[4][4][4];
        #pragma unroll
        for (int t = 0; t < 4; t++)
            #pragma unroll
            for (int j = 0; j < 4; j++)
                #pragma unroll
                for (int q = 0; q < 4; q++)
                    acc[t][j][q] = 0.0f;

        auto produce = [&](int stage, int kb) {
            float* As = smem + stage * TSTAGE_WORDS;
            float* Bs = As + BM * LDSS;
            const float* Ag = Abase + (size_t)prow * KDIM + kb * BK + pcc * 4;
            const float* Bg = Bbase + (size_t)prow * KDIM + kb * BK + pcc * 4;
            #pragma unroll
            for (int j = 0; j < 4; j++) {
                cp_async16(smem_u32(As + (prow + 32 * j) * LDSS + pcc * 4),
                           Ag + (size_t)(32 * j) * KDIM);
                cp_async16(smem_u32(Bs + (prow + 32 * j) * LDSS + pcc * 4),
                           Bg + (size_t)(32 * j) * KDIM);
            }
        };

        produce(0, 0); cp_commit();
        produce(1, 1); cp_commit();

        int stage = 0;
        for (int it = 0; it < KITERS; ++it) {
            cp_wait1();
            bar_sync(1, 256);

            if (it + 2 < KITERS) {
                int ps = stage + 2; if (ps >= TSTAGES) ps -= TSTAGES;
                produce(ps, it + 2);
            }
            cp_commit();

            const uint32_t* Au = (const uint32_t*)(smem + stage * TSTAGE_WORDS);
            const uint32_t* Bu = Au + BM * LDSS;

            #pragma unroll
            for (int ks = 0; ks < 4; ks++) {
                const int k0 = ks * 8 + tig;
                uint32_t a[4][4], b[4][2];
                #pragma unroll
                for (int t = 0; t < 4; t++) {
                    const int r = warp_m * 64 + t * 16 + grp;
                    a[t][0] = Au[r * LDSS + k0];
                    a[t][1] = Au[(r + 8) * LDSS + k0];
                    a[t][2] = Au[r * LDSS + k0 + 4];
                    a[t][3] = Au[(r + 8) * LDSS + k0 + 4];
                }
                #pragma unroll
                for (int j = 0; j < 4; j++) {
                    const int n = warp_n * 32 + j * 8 + grp;
                    b[j][0] = Bu[n * LDSS + k0];
                    b[j][1] = Bu[n * LDSS + k0 + 4];
                }
                #pragma unroll
                for (int t = 0; t < 4; t++)
                    #pragma unroll
                    for (int j = 0; j < 4; j++)
                        mma_m16n8k8(acc[t][j], a[t], b[j]);
            }

            if (++stage == TSTAGES) stage = 0;
        }

        #pragma unroll
        for (int t = 0; t < 4; t++) {
            const int r0 = m_base + warp_m * 64 + t * 16 + grp;
            #pragma unroll
            for (int j = 0; j < 4; j++) {
                const int cg = n_base + warp_n * 32 + j * 8 + 2 * tig;
                float2 v0 = make_float2(acc[t][j][0], acc[t][j][1]);
                float2 v1 = make_float2(acc[t][j][2], acc[t][j][3]);
                *reinterpret_cast<float2*>(out + (size_t)r0 * NDIM + cg) = v0;
                *reinterpret_cast<float2*>(out + (size_t)(r0 + 8) * NDIM + cg) = v1;
            }
        }
    } else {
        // ================= SIMT ROLE: 4 warps, fp32 FFMA, 64x64 tile ==========
        const int cid = blockIdx.y * gridDim.x + blockIdx.x;
        if (cid >= SIMT_TILES) return;   // no SIMT tile for this CTA

        const int tm = cid % SIMT_MT;         // m-tile
        const int tn = cid / SIMT_MT;         // n-tile (0..7)
        const int m0 = tm * 64;
        const int n0 = NT + tn * 64;

        const int ts = tid - 256;             // 0..127
        const int tx = ts & 15;               // col group (4 cols)
        const int ty = ts >> 4;               // row group (8 rows)

        float* sbase = smem + TENSOR_WORDS;

        float acc[8][4];
        #pragma unroll
        for (int i = 0; i < 8; i++)
            #pragma unroll
            for (int j = 0; j < 4; j++)
                acc[i][j] = 0.0f;

        // stage layout: [A: 32k x 68][B: 32k x 68], k-major (transposed on load)
        auto sproduce = [&](int stage, int kb) {
            float* SA = sbase + stage * SSTAGE_WORDS;
            float* SB = SA + BK * SP;
            #pragma unroll
            for (int i = 0; i < 16; i++) {
                const int w = ts + 128 * i;   // 0..2047
                const int r = w >> 5;          // 0..63
                const int k = w & 31;
                cp_async4(smem_u32(SA + k * SP + r),
                          Aorig + (size_t)(m0 + r) * KDIM + kb * BK + k);
                cp_async4(smem_u32(SB + k * SP + r),
                          Worig + (size_t)(n0 + r) * KDIM + kb * BK + k);
            }
        };

        sproduce(0, 0); cp_commit();
        sproduce(1, 1); cp_commit();

        for (int kb = 0; kb < KITERS; ++kb) {
            const int stage = kb & 1;
            cp_wait1();
            bar_sync(2, 128);   // stage kb visible to all SIMT threads

            const float* SA = sbase + stage * SSTAGE_WORDS;
            const float* SB = SA + BK * SP;

            #pragma unroll
            for (int k = 0; k < BK; k++) {
                float4 a0 = *reinterpret_cast<const float4*>(SA + k * SP + ty * 8);
                float4 a1 = *reinterpret_cast<const float4*>(SA + k * SP + ty * 8 + 4);
                float4 b0 = *reinterpret_cast<const float4*>(SB + k * SP + tx * 4);
                const float av[8] = {a0.x, a0.y, a0.z, a0.w, a1.x, a1.y, a1.z, a1.w};
                const float bv[4] = {b0.x, b0.y, b0.z, b0.w};
                #pragma unroll
                for (int i = 0; i < 8; i++)
                    #pragma unroll
                    for (int j = 0; j < 4; j++)
                        acc[i][j] += av[i] * bv[j];
            }

            bar_sync(2, 128);   // all reads of this stage done
            if (kb + 2 < KITERS) sproduce(stage, kb + 2);
            cp_commit();
        }

        #pragma unroll
        for (int i = 0; i < 8; i++) {
            const int row = m0 + ty * 8 + i;
            float4 v = make_float4(acc[i][0], acc[i][1], acc[i][2], acc[i][3]);
            *reinterpret_cast<float4*>(out + (size_t)row * NDIM + n0 + tx * 4) = v;
        }
    }
}

// ------------------------------- launch --------------------------------------

extern "C" void kernel_launch(void* const* d_in, const int* in_sizes, int n_in,
                              void* d_out, int out_size) {
    const float* A = (const float*)d_in[0];   // [8,1024,4096] == [8192,4096]
    const float* W = (const float*)d_in[1];   // [4096,4096] (N,K)
    float* out = (float*)d_out;               // [8192,4096]
    (void)in_sizes; (void)n_in; (void)out_size;

    cudaFuncSetAttribute(gemm_kernel,
                         cudaFuncAttributeMaxDynamicSharedMemorySize, SMEM_TOTAL);

    prepass_kernel<<<1184, 256>>>(A, W);

    dim3 grid(NT / BN, MTOT / BM);   // (28, 64) = 1792 CTAs
    gemm_kernel<<<grid, 384, SMEM_TOTAL>>>(out, A, W);
}

// round 6
// speedup vs baseline: 1.5010x; 1.5010x over previous
#include <cuda_runtime.h>
#include <cstdint>

// ---------------------------------------------------------------------------
// C[8192,4096] = A[8192,4096] * W[4096,4096]^T  (fp32 in/out)
// tf32 mma.sync.m16n8k8 (harness targets base sm_103; no tcgen05).
// R6: R3 config (BM=256, BN=128, BK=32, 256 thr, warp tile 64x64, 4-stage
// cp.async) + ldmatrix.x4 fragment loads (4x fewer shared-load issues).
// ---------------------------------------------------------------------------

#define MTOT 8192
#define KDIM 4096
#define NDIM 4096

#define BM 256
#define BN 128
#define BK 32
#define KITERS (KDIM / BK)        // 128
#define STAGES 4

#define LDSS 36                    // padded row stride in words (32 + 4)
#define STAGE_WORDS ((BM + BN) * LDSS)          // 13824 words = 55296 B
#define STAGE_BYTES (STAGE_WORDS * 4)
#define SMEM_TOTAL (STAGES * STAGE_BYTES)       // 221184 B

// tf32-rounded scratch copies (device globals: allowed, no allocation)
__device__ float g_A[(size_t)MTOT * KDIM];
__device__ float g_W[(size_t)NDIM * KDIM];

// ------------------------------- helpers -----------------------------------

__device__ __forceinline__ uint32_t smem_u32(const void* p) {
    uint32_t a;
    asm("{ .reg .u64 t; cvta.to.shared.u64 t, %1; cvt.u32.u64 %0, t; }"
        : "=r"(a) : "l"(p));
    return a;
}

__device__ __forceinline__ float tf32_round(float x) {
    uint32_t u;
    asm("cvt.rna.tf32.f32 %0, %1;" : "=r"(u) : "f"(x));
    return __uint_as_float(u);
}

__device__ __forceinline__ void cp_async16(uint32_t dst, const void* src) {
    asm volatile("cp.async.cg.shared.global [%0], [%1], 16;\n"
                 :: "r"(dst), "l"(src) : "memory");
}
__device__ __forceinline__ void cp_commit() {
    asm volatile("cp.async.commit_group;\n" ::: "memory");
}
__device__ __forceinline__ void cp_wait2() {
    asm volatile("cp.async.wait_group 2;\n" ::: "memory");
}

// ldmatrix x4 on tf32 data (each b16 8x8 matrix == one 8row x 4col tf32 block)
__device__ __forceinline__ void ldsm_x4(uint32_t& r0, uint32_t& r1,
                                        uint32_t& r2, uint32_t& r3,
                                        uint32_t addr) {
    asm volatile("ldmatrix.sync.aligned.m8n8.x4.shared.b16 {%0,%1,%2,%3}, [%4];"
                 : "=r"(r0), "=r"(r1), "=r"(r2), "=r"(r3) : "r"(addr));
}

__device__ __forceinline__ void mma_m16n8k8(float* c, const uint32_t* a,
                                            const uint32_t* b) {
    asm volatile(
        "mma.sync.aligned.m16n8k8.row.col.f32.tf32.tf32.f32 "
        "{%0,%1,%2,%3}, {%4,%5,%6,%7}, {%8,%9}, {%0,%1,%2,%3};"
        : "+f"(c[0]), "+f"(c[1]), "+f"(c[2]), "+f"(c[3])
        : "r"(a[0]), "r"(a[1]), "r"(a[2]), "r"(a[3]),
          "r"(b[0]), "r"(b[1]));
}

// ------------------------------- prepass ------------------------------------

__global__ void __launch_bounds__(256) prepass_kernel(const float* __restrict__ A,
                                                      const float* __restrict__ W) {
    const long long nA = (long long)MTOT * KDIM / 4;
    const long long nW = (long long)NDIM * KDIM / 4;
    const long long stride = (long long)gridDim.x * blockDim.x;
    for (long long i = (long long)blockIdx.x * blockDim.x + threadIdx.x;
         i < nA + nW; i += stride) {
        const float4* src;
        float4* dst;
        long long j;
        if (i < nA) { src = (const float4*)A; dst = (float4*)g_A; j = i; }
        else        { src = (const float4*)W; dst = (float4*)g_W; j = i - nA; }
        float4 v = src[j];
        v.x = tf32_round(v.x);
        v.y = tf32_round(v.y);
        v.z = tf32_round(v.z);
        v.w = tf32_round(v.w);
        dst[j] = v;
    }
}

// ------------------------------- GEMM ---------------------------------------

__global__ void __launch_bounds__(256, 1) gemm_kernel(float* __restrict__ out) {
    extern __shared__ float smem[];
    const uint32_t sbase = smem_u32(smem);
    const int tid = threadIdx.x;
    const int lane = tid & 31;
    const int wid = tid >> 5;
    const int warp_m = wid & 3;       // 0..3 -> 64-row strip
    const int warp_n = wid >> 2;      // 0..1 -> 64-col strip
    const int grp = lane >> 2;        // groupID (0..7)
    const int tig = lane & 3;         // threadID-in-group (0..3)

    const int m_base = blockIdx.y * BM;
    const int n_base = blockIdx.x * BN;

    const float* Abase = g_A + (size_t)m_base * KDIM;
    const float* Bbase = g_W + (size_t)n_base * KDIM;

    // producer geometry: A = 2048 16B chunks/stage, B = 1024 -> 12 per thread
    const int prow = tid >> 3;        // 0..31
    const int pcc = tid & 7;          // 16B chunk within 128B of K

    // --- ldmatrix per-lane base addresses (within stage 0) ---
    const int lj = lane >> 3;         // matrix index 0..3
    const int lr = lane & 7;          // row within matrix
    // A matrices: j -> (m-half = j&1, k-half = j>>1)
    const uint32_t a_lane = sbase
        + (uint32_t)(((warp_m * 64 + (lj & 1) * 8 + lr) * LDSS + (lj >> 1) * 4) * 4);
    // B matrices: j -> (n-sub = j>>1, k-half = j&1); B region starts at BM*LDSS
    const uint32_t b_lane = sbase + (uint32_t)(BM * LDSS * 4)
        + (uint32_t)(((warp_n * 64 + (lj >> 1) * 8 + lr) * LDSS + (lj & 1) * 4) * 4);

    float acc[4][8][4];
    #pragma unroll
    for (int t = 0; t < 4; t++)
        #pragma unroll
        for (int j = 0; j < 8; j++)
            #pragma unroll
            for (int q = 0; q < 4; q++)
                acc[t][j][q] = 0.0f;

    auto produce = [&](int stage, int kb) {
        float* As = smem + stage * STAGE_WORDS;
        float* Bs = As + BM * LDSS;
        const float* Ag = Abase + (size_t)prow * KDIM + kb * BK + pcc * 4;
        const float* Bg = Bbase + (size_t)prow * KDIM + kb * BK + pcc * 4;
        #pragma unroll
        for (int j = 0; j < 8; j++)
            cp_async16(smem_u32(As + (prow + 32 * j) * LDSS + pcc * 4),
                       Ag + (size_t)(32 * j) * KDIM);
        #pragma unroll
        for (int j = 0; j < 4; j++)
            cp_async16(smem_u32(Bs + (prow + 32 * j) * LDSS + pcc * 4),
                       Bg + (size_t)(32 * j) * KDIM);
    };

    // prologue: fill 3 of 4 stages
    produce(0, 0); cp_commit();
    produce(1, 1); cp_commit();
    produce(2, 2); cp_commit();

    for (int it = 0; it < KITERS; ++it) {
        const int stage = it & 3;

        cp_wait2();          // stage `it` fully resident (<=2 groups pending)
        __syncthreads();     // all reads of stage it-1 done; safe to refill

        if (it + 3 < KITERS) produce((it + 3) & 3, it + 3);
        cp_commit();         // fixed group count per iteration

        const uint32_t aS = a_lane + (uint32_t)(stage * STAGE_BYTES);
        const uint32_t bS = b_lane + (uint32_t)(stage * STAGE_BYTES);

        #pragma unroll
        for (int ks = 0; ks < 4; ks++) {
            const uint32_t koff = (uint32_t)(ks * 8 * 4);
            uint32_t a[4][4], b[8][2];
            // A fragments: 4 ldmatrix.x4 (one per 16-row m-tile)
            #pragma unroll
            for (int t = 0; t < 4; t++)
                ldsm_x4(a[t][0], a[t][1], a[t][2], a[t][3],
                        aS + koff + (uint32_t)(t * 16 * LDSS * 4));
            // B fragments: 4 ldmatrix.x4 (one per 16-col n-pair)
            #pragma unroll
            for (int p = 0; p < 4; p++)
                ldsm_x4(b[2 * p][0], b[2 * p][1], b[2 * p + 1][0], b[2 * p + 1][1],
                        bS + koff + (uint32_t)(p * 16 * LDSS * 4));
            #pragma unroll
            for (int t = 0; t < 4; t++)
                #pragma unroll
                for (int j = 0; j < 8; j++)
                    mma_m16n8k8(acc[t][j], a[t], b[j]);
        }
    }

    // epilogue: float2 stores, 32B-sector aligned
    #pragma unroll
    for (int t = 0; t < 4; t++) {
        const int r0 = m_base + warp_m * 64 + t * 16 + grp;
        #pragma unroll
        for (int j = 0; j < 8; j++) {
            const int cg = n_base + warp_n * 64 + j * 8 + 2 * tig;
            float2 v0 = make_float2(acc[t][j][0], acc[t][j][1]);
            float2 v1 = make_float2(acc[t][j][2], acc[t][j][3]);
            *reinterpret_cast<float2*>(out + (size_t)r0 * NDIM + cg) = v0;
            *reinterpret_cast<float2*>(out + (size_t)(r0 + 8) * NDIM + cg) = v1;
        }
    }
}

// ------------------------------- launch --------------------------------------

extern "C" void kernel_launch(void* const* d_in, const int* in_sizes, int n_in,
                              void* d_out, int out_size) {
    const float* A = (const float*)d_in[0];   // [8,1024,4096] == [8192,4096]
    const float* W = (const float*)d_in[1];   // [4096,4096] (N,K)
    float* out = (float*)d_out;               // [8192,4096]
    (void)in_sizes; (void)n_in; (void)out_size;

    cudaFuncSetAttribute(gemm_kernel,
                         cudaFuncAttributeMaxDynamicSharedMemorySize, SMEM_TOTAL);

    prepass_kernel<<<1184, 256>>>(A, W);

    dim3 grid(NDIM / BN, MTOT / BM);   // (32, 32) = 1024 CTAs
    gemm_kernel<<<grid, 256, SMEM_TOTAL>>>(out);
}